// round 1
// baseline (speedup 1.0000x reference)
#include <cuda_runtime.h>
#include <cuda_bf16.h>
#include <cstdint>

// GroupLinear: y[b, g*64+o] = sum_i x[b, g*64+i] * W[g*64+o, g*64+i]
// 64 independent [8192x64] x [64x64]^T GEMMs, fp32.
//
// Strategy: CUDA-core kernel using Blackwell packed fma.rn.f32x2 (2 FMAs per
// issue slot) with f32x2 lanes running along K, so x and W are consumed in
// natural K-major layout (no transpose, no packing movs). One CTA = one group
// x 128 tokens. W block + x tile staged in shared memory.

#define N_TOKENS   8192
#define IN_CH      4096
#define GROUPS     64
#define GS         64          // group size (in = out = 64)
#define BLK_TOK    128
#define TM         4           // tokens per thread (stride-32 assignment)
#define TN         8           // outputs per thread
#define THREADS    256
#define XS_STRIDE  68          // 64 + 4 pad; 68/4=17 odd -> conflict-free strided LDS.128

// d = a*b + d, elementwise on packed f32x2 (two fp32 lanes per 64-bit reg)
__device__ __forceinline__ void fma2(unsigned long long& d,
                                     unsigned long long a,
                                     unsigned long long b) {
    asm volatile("fma.rn.f32x2 %0, %1, %2, %0;" : "+l"(d) : "l"(a), "l"(b));
}

__device__ __forceinline__ float f32x2_hsum(unsigned long long a) {
    float lo, hi;
    asm("mov.b64 {%0, %1}, %2;" : "=f"(lo), "=f"(hi) : "l"(a));
    return lo + hi;
}

__global__ __launch_bounds__(THREADS, 2)
void group_linear_kernel(const float* __restrict__ x,
                         const float* __restrict__ w,
                         float* __restrict__ y) {
    extern __shared__ float smem[];
    float* ws = smem;                  // [GS][GS]      = 64*64 floats (K-major rows)
    float* xs = smem + GS * GS;        // [BLK_TOK][68] padded rows, K-major

    const int g    = blockIdx.y;
    const int tok0 = blockIdx.x * BLK_TOK;
    const int tid  = threadIdx.x;

    // ---- Load W diagonal block g: ws[o][k] = W[g*64+o][g*64+k] ----
    // 4096 floats = 1024 float4; 4 per thread. Coalesced; natural layout.
    {
        const float4* __restrict__ wsrc = reinterpret_cast<const float4*>(w);
        #pragma unroll
        for (int r = 0; r < 4; r++) {
            int idx = tid + r * THREADS;        // float4 index 0..1023
            int o   = idx >> 4;                 // 0..63
            int k4  = idx & 15;                 // 0..15
            float4 v = wsrc[((size_t)(g * GS + o) * IN_CH + g * GS) / 4 + k4];
            *reinterpret_cast<float4*>(ws + o * GS + k4 * 4) = v;
        }
    }

    // ---- Load x tile: xs[t][k] = x[tok0+t][g*64+k], padded stride 68 ----
    // 8192 floats = 2048 float4; 8 per thread. Coalesced loads; STS.128 at
    // phase (t + k4) mod 8 -> minimal 4-phase.
    {
        const float4* __restrict__ xsrc = reinterpret_cast<const float4*>(x);
        #pragma unroll
        for (int r = 0; r < 8; r++) {
            int idx = tid + r * THREADS;        // 0..2047
            int t   = idx >> 4;                 // 0..127
            int k4  = idx & 15;                 // 0..15
            float4 v = xsrc[((size_t)(tok0 + t) * IN_CH + g * GS) / 4 + k4];
            *reinterpret_cast<float4*>(xs + t * XS_STRIDE + k4 * 4) = v;
        }
    }

    __syncthreads();

    const int lane = tid & 31;
    const int og   = tid >> 5;   // 0..7 -> outputs og*8 .. og*8+7
    // thread's tokens: lane + 32*t  (t = 0..3) -> strided, conflict-free LDS

    unsigned long long acc[TM][TN];
    #pragma unroll
    for (int t = 0; t < TM; t++)
        #pragma unroll
        for (int o = 0; o < TN; o++)
            acc[t][o] = 0ull;

    #pragma unroll
    for (int k = 0; k < GS; k += 4) {
        // x chunk: 4 tokens x 4 k-values, each LDS.128 = 2 packed f32x2
        ulonglong2 xv[TM];
        #pragma unroll
        for (int t = 0; t < TM; t++)
            xv[t] = *reinterpret_cast<const ulonglong2*>(
                        xs + (lane + 32 * t) * XS_STRIDE + k);

        #pragma unroll
        for (int o = 0; o < TN; o++) {
            // broadcast LDS.128: all lanes in warp read same W row chunk
            ulonglong2 wv = *reinterpret_cast<const ulonglong2*>(
                                ws + (og * TN + o) * GS + k);
            #pragma unroll
            for (int t = 0; t < TM; t++) {
                fma2(acc[t][o], xv[t].x, wv.x);
                fma2(acc[t][o], xv[t].y, wv.y);
            }
        }
    }

    // ---- Epilogue: horizontal sum of each f32x2 acc, vectorized stores ----
    #pragma unroll
    for (int t = 0; t < TM; t++) {
        int tok = tok0 + lane + 32 * t;
        float4 r0, r1;
        r0.x = f32x2_hsum(acc[t][0]);
        r0.y = f32x2_hsum(acc[t][1]);
        r0.z = f32x2_hsum(acc[t][2]);
        r0.w = f32x2_hsum(acc[t][3]);
        r1.x = f32x2_hsum(acc[t][4]);
        r1.y = f32x2_hsum(acc[t][5]);
        r1.z = f32x2_hsum(acc[t][6]);
        r1.w = f32x2_hsum(acc[t][7]);
        float4* dst = reinterpret_cast<float4*>(
            y + (size_t)tok * IN_CH + g * GS + og * TN);
        dst[0] = r0;
        dst[1] = r1;
    }
}

extern "C" void kernel_launch(void* const* d_in, const int* in_sizes, int n_in,
                              void* d_out, int out_size) {
    const float* x = (const float*)d_in[0];   // [8192, 4096] fp32
    const float* w = (const float*)d_in[1];   // [4096, 4096] fp32
    float* y = (float*)d_out;                 // [8192, 4096] fp32

    const int smem_bytes = (GS * GS + BLK_TOK * XS_STRIDE) * (int)sizeof(float); // 51200
    cudaFuncSetAttribute(group_linear_kernel,
                         cudaFuncAttributeMaxDynamicSharedMemorySize, smem_bytes);

    dim3 grid(N_TOKENS / BLK_TOK, GROUPS);    // (64, 64)
    group_linear_kernel<<<grid, THREADS, smem_bytes>>>(x, w, y);
}

// round 2
// speedup vs baseline: 1.0003x; 1.0003x over previous
#include <cuda_runtime.h>
#include <cuda_bf16.h>
#include <cstdint>

// GroupLinear: y[b, g*64+o] = sum_i x[b, g*64+i] * W[g*64+o, g*64+i]
// 64 independent [8192x64] x [64x64]^T GEMMs, fp32.
//
// Strategy: CUDA-core kernel using Blackwell packed fma.rn.f32x2 (2 FMAs per
// issue slot) with f32x2 lanes running along K, so x and W are consumed in
// natural K-major layout (no transpose, no packing movs). One CTA = one group
// x 128 tokens. W block + x tile staged in shared memory.

#define N_TOKENS   8192
#define IN_CH      4096
#define GROUPS     64
#define GS         64          // group size (in = out = 64)
#define BLK_TOK    128
#define TM         4           // tokens per thread (stride-32 assignment)
#define TN         8           // outputs per thread
#define THREADS    256
#define XS_STRIDE  68          // 64 + 4 pad; 68/4=17 odd -> conflict-free strided LDS.128

// d = a*b + d, elementwise on packed f32x2 (two fp32 lanes per 64-bit reg)
__device__ __forceinline__ void fma2(unsigned long long& d,
                                     unsigned long long a,
                                     unsigned long long b) {
    asm volatile("fma.rn.f32x2 %0, %1, %2, %0;" : "+l"(d) : "l"(a), "l"(b));
}

__device__ __forceinline__ float f32x2_hsum(unsigned long long a) {
    float lo, hi;
    asm("mov.b64 {%0, %1}, %2;" : "=f"(lo), "=f"(hi) : "l"(a));
    return lo + hi;
}

__global__ __launch_bounds__(THREADS, 2)
void group_linear_kernel(const float* __restrict__ x,
                         const float* __restrict__ w,
                         float* __restrict__ y) {
    extern __shared__ float smem[];
    float* ws = smem;                  // [GS][GS]      = 64*64 floats (K-major rows)
    float* xs = smem + GS * GS;        // [BLK_TOK][68] padded rows, K-major

    const int g    = blockIdx.y;
    const int tok0 = blockIdx.x * BLK_TOK;
    const int tid  = threadIdx.x;

    // ---- Load W diagonal block g: ws[o][k] = W[g*64+o][g*64+k] ----
    // 4096 floats = 1024 float4; 4 per thread. Coalesced; natural layout.
    {
        const float4* __restrict__ wsrc = reinterpret_cast<const float4*>(w);
        #pragma unroll
        for (int r = 0; r < 4; r++) {
            int idx = tid + r * THREADS;        // float4 index 0..1023
            int o   = idx >> 4;                 // 0..63
            int k4  = idx & 15;                 // 0..15
            float4 v = wsrc[((size_t)(g * GS + o) * IN_CH + g * GS) / 4 + k4];
            *reinterpret_cast<float4*>(ws + o * GS + k4 * 4) = v;
        }
    }

    // ---- Load x tile: xs[t][k] = x[tok0+t][g*64+k], padded stride 68 ----
    // 8192 floats = 2048 float4; 8 per thread. Coalesced loads; STS.128 at
    // phase (t + k4) mod 8 -> minimal 4-phase.
    {
        const float4* __restrict__ xsrc = reinterpret_cast<const float4*>(x);
        #pragma unroll
        for (int r = 0; r < 8; r++) {
            int idx = tid + r * THREADS;        // 0..2047
            int t   = idx >> 4;                 // 0..127
            int k4  = idx & 15;                 // 0..15
            float4 v = xsrc[((size_t)(tok0 + t) * IN_CH + g * GS) / 4 + k4];
            *reinterpret_cast<float4*>(xs + t * XS_STRIDE + k4 * 4) = v;
        }
    }

    __syncthreads();

    const int lane = tid & 31;
    const int og   = tid >> 5;   // 0..7 -> outputs og*8 .. og*8+7
    // thread's tokens: lane + 32*t  (t = 0..3) -> strided, conflict-free LDS

    unsigned long long acc[TM][TN];
    #pragma unroll
    for (int t = 0; t < TM; t++)
        #pragma unroll
        for (int o = 0; o < TN; o++)
            acc[t][o] = 0ull;

    #pragma unroll
    for (int k = 0; k < GS; k += 4) {
        // x chunk: 4 tokens x 4 k-values, each LDS.128 = 2 packed f32x2
        ulonglong2 xv[TM];
        #pragma unroll
        for (int t = 0; t < TM; t++)
            xv[t] = *reinterpret_cast<const ulonglong2*>(
                        xs + (lane + 32 * t) * XS_STRIDE + k);

        #pragma unroll
        for (int o = 0; o < TN; o++) {
            // broadcast LDS.128: all lanes in warp read same W row chunk
            ulonglong2 wv = *reinterpret_cast<const ulonglong2*>(
                                ws + (og * TN + o) * GS + k);
            #pragma unroll
            for (int t = 0; t < TM; t++) {
                fma2(acc[t][o], xv[t].x, wv.x);
                fma2(acc[t][o], xv[t].y, wv.y);
            }
        }
    }

    // ---- Epilogue: horizontal sum of each f32x2 acc, vectorized stores ----
    #pragma unroll
    for (int t = 0; t < TM; t++) {
        int tok = tok0 + lane + 32 * t;
        float4 r0, r1;
        r0.x = f32x2_hsum(acc[t][0]);
        r0.y = f32x2_hsum(acc[t][1]);
        r0.z = f32x2_hsum(acc[t][2]);
        r0.w = f32x2_hsum(acc[t][3]);
        r1.x = f32x2_hsum(acc[t][4]);
        r1.y = f32x2_hsum(acc[t][5]);
        r1.z = f32x2_hsum(acc[t][6]);
        r1.w = f32x2_hsum(acc[t][7]);
        float4* dst = reinterpret_cast<float4*>(
            y + (size_t)tok * IN_CH + g * GS + og * TN);
        dst[0] = r0;
        dst[1] = r1;
    }
}

extern "C" void kernel_launch(void* const* d_in, const int* in_sizes, int n_in,
                              void* d_out, int out_size) {
    const float* x = (const float*)d_in[0];   // [8192, 4096] fp32
    const float* w = (const float*)d_in[1];   // [4096, 4096] fp32
    float* y = (float*)d_out;                 // [8192, 4096] fp32

    const int smem_bytes = (GS * GS + BLK_TOK * XS_STRIDE) * (int)sizeof(float); // 51200
    cudaFuncSetAttribute(group_linear_kernel,
                         cudaFuncAttributeMaxDynamicSharedMemorySize, smem_bytes);

    dim3 grid(N_TOKENS / BLK_TOK, GROUPS);    // (64, 64)
    group_linear_kernel<<<grid, THREADS, smem_bytes>>>(x, w, y);
}

// round 7
// speedup vs baseline: 1.4762x; 1.4758x over previous
#include <cuda_runtime.h>
#include <cuda_bf16.h>
#include <cstdint>

// GroupLinear: y[b, g*64+o] = sum_i x[b, g*64+i] * W[g*64+o, g*64+i]
// 64 independent [8192x64] x [64x64]^T GEMMs, fp32 in/out.
//
// Harness compiles at virtual arch compute_100 => tcgen05 unavailable.
// Use legacy mma.sync.m16n8k16 bf16 (sm_80+ PTX) with 2-term bf16 split:
//   x = xh + xl, W = wh + wl;  y ≈ xh*wh + xh*wl + xl*wh   (drop lo*lo ~2^-16)
// One CTA = (group g, 128 tokens): M=128, N=64, K=64. 4 warps, each warp
// owns 32 M-rows x all 64 N-cols. fp32 accumulate in registers.

#define GROUPS     64
#define GS         64
#define BLK_TOK    128
#define THREADS    128
#define IN_CH      4096
#define N_TOKENS   8192

// SMEM (bytes): bf16 tiles, stride 72 halves (144 B) -> conflict-free frags
#define XSTRIDE_H  72
#define SM_XH      0
#define SM_XL      (SM_XH + BLK_TOK * XSTRIDE_H * 2)     // 18432
#define SM_WH      (SM_XL + BLK_TOK * XSTRIDE_H * 2)     // 36864
#define SM_WL      (SM_WH + GS * XSTRIDE_H * 2)          // 46080
#define SM_TOTAL   (SM_WL + GS * XSTRIDE_H * 2)          // 55296
// Epilogue staging reuses XH/XL space (after syncthreads):
#define YS_STRIDE  68                                    // floats
#define SM_YS      0                                     // 128*68*4 = 34816 B

__device__ __forceinline__ uint32_t pack_bf16(float a, float b) {
    __nv_bfloat162 t = __floats2bfloat162_rn(a, b);   // .x = a (low), .y = b
    return *reinterpret_cast<uint32_t*>(&t);
}

// split v into bf16 hi + bf16 lo (captures next 8 mantissa bits)
__device__ __forceinline__ void split_bf16(float v, float& hi, float& lo) {
    hi = __bfloat162float(__float2bfloat16(v));
    lo = v - hi;
}

__device__ __forceinline__ void mma_bf16(float* c, const uint32_t* a,
                                         const uint32_t* b) {
    asm volatile(
        "mma.sync.aligned.m16n8k16.row.col.f32.bf16.bf16.f32 "
        "{%0,%1,%2,%3}, {%4,%5,%6,%7}, {%8,%9}, {%0,%1,%2,%3};"
        : "+f"(c[0]), "+f"(c[1]), "+f"(c[2]), "+f"(c[3])
        : "r"(a[0]), "r"(a[1]), "r"(a[2]), "r"(a[3]), "r"(b[0]), "r"(b[1]));
}

__global__ __launch_bounds__(THREADS, 2)
void group_linear_mma(const float* __restrict__ x,
                      const float* __restrict__ w,
                      float* __restrict__ y) {
    extern __shared__ char smem[];
    const int tid  = threadIdx.x;
    const int wid  = tid >> 5;
    const int lane = tid & 31;
    const int g    = blockIdx.y;
    const int tok0 = blockIdx.x * BLK_TOK;

    // ---- Load W diagonal block g -> bf16 hi/lo smem ----
    // 64x64 f32 = 1024 float4; 8 per thread. Coalesced.
    {
        #pragma unroll
        for (int r = 0; r < 8; r++) {
            int idx = tid + r * THREADS;            // 0..1023
            int row = idx >> 4;                     // 0..63 (output o)
            int k4  = idx & 15;                     // float4 index along K
            float4 v = *reinterpret_cast<const float4*>(
                w + (size_t)(g * GS + row) * IN_CH + g * GS + k4 * 4);
            float hx, lx, hy, ly, hz, lz, hw, lw;
            split_bf16(v.x, hx, lx); split_bf16(v.y, hy, ly);
            split_bf16(v.z, hz, lz); split_bf16(v.w, hw, lw);
            uint2 hp = make_uint2(pack_bf16(hx, hy), pack_bf16(hz, hw));
            uint2 lp = make_uint2(pack_bf16(lx, ly), pack_bf16(lz, lw));
            int off = (row * XSTRIDE_H + k4 * 4) * 2;       // bytes
            *reinterpret_cast<uint2*>(smem + SM_WH + off) = hp;
            *reinterpret_cast<uint2*>(smem + SM_WL + off) = lp;
        }
    }

    // ---- Load x tile [128 x 64] -> bf16 hi/lo smem ----
    {
        #pragma unroll
        for (int r = 0; r < 16; r++) {
            int idx = tid + r * THREADS;            // 0..2047
            int row = idx >> 4;                     // 0..127 (token)
            int k4  = idx & 15;
            float4 v = *reinterpret_cast<const float4*>(
                x + (size_t)(tok0 + row) * IN_CH + g * GS + k4 * 4);
            float hx, lx, hy, ly, hz, lz, hw, lw;
            split_bf16(v.x, hx, lx); split_bf16(v.y, hy, ly);
            split_bf16(v.z, hz, lz); split_bf16(v.w, hw, lw);
            uint2 hp = make_uint2(pack_bf16(hx, hy), pack_bf16(hz, hw));
            uint2 lp = make_uint2(pack_bf16(lx, ly), pack_bf16(lz, lw));
            int off = (row * XSTRIDE_H + k4 * 4) * 2;
            *reinterpret_cast<uint2*>(smem + SM_XH + off) = hp;
            *reinterpret_cast<uint2*>(smem + SM_XL + off) = lp;
        }
    }
    __syncthreads();

    // ---- Mainloop: warp owns M-rows [wid*32, wid*32+32), all N=64 ----
    // Canonical m16n8k16 fragment maps:
    //  A reg i: row = base + (lane>>2) + (i&1)*8, k = k0 + (lane%4)*2 + (i>>1)*8
    //  B reg i: n = nt*8 + (lane>>2),            k = k0 + (lane%4)*2 + i*8
    //  C reg i: row = base + (lane>>2) + (i>>1)*8, col = nt*8 + (lane%4)*2 + (i&1)
    const int wrow = wid * 32;
    const int lane_ab = ((lane >> 2) * XSTRIDE_H + (lane & 3) * 2) * 2; // bytes

    float acc[2][8][4];
    #pragma unroll
    for (int mt = 0; mt < 2; mt++)
        #pragma unroll
        for (int nt = 0; nt < 8; nt++)
            #pragma unroll
            for (int i = 0; i < 4; i++)
                acc[mt][nt][i] = 0.0f;

    #pragma unroll
    for (int kk = 0; kk < 4; kk++) {
        const int k0b = kk * 16 * 2;               // k-step byte offset

        uint32_t ah[2][4], al[2][4];
        #pragma unroll
        for (int mt = 0; mt < 2; mt++) {
            int base = (wrow + mt * 16) * XSTRIDE_H * 2 + k0b + lane_ab;
            const char* ph = smem + SM_XH + base;
            const char* pl = smem + SM_XL + base;
            ah[mt][0] = *reinterpret_cast<const uint32_t*>(ph);
            ah[mt][1] = *reinterpret_cast<const uint32_t*>(ph + 8 * XSTRIDE_H * 2);
            ah[mt][2] = *reinterpret_cast<const uint32_t*>(ph + 16);
            ah[mt][3] = *reinterpret_cast<const uint32_t*>(ph + 8 * XSTRIDE_H * 2 + 16);
            al[mt][0] = *reinterpret_cast<const uint32_t*>(pl);
            al[mt][1] = *reinterpret_cast<const uint32_t*>(pl + 8 * XSTRIDE_H * 2);
            al[mt][2] = *reinterpret_cast<const uint32_t*>(pl + 16);
            al[mt][3] = *reinterpret_cast<const uint32_t*>(pl + 8 * XSTRIDE_H * 2 + 16);
        }

        #pragma unroll
        for (int nt = 0; nt < 8; nt++) {
            int base = (nt * 8) * XSTRIDE_H * 2 + k0b + lane_ab;
            const char* ph = smem + SM_WH + base;
            const char* pl = smem + SM_WL + base;
            uint32_t bh[2], bl[2];
            bh[0] = *reinterpret_cast<const uint32_t*>(ph);
            bh[1] = *reinterpret_cast<const uint32_t*>(ph + 16);
            bl[0] = *reinterpret_cast<const uint32_t*>(pl);
            bl[1] = *reinterpret_cast<const uint32_t*>(pl + 16);
            #pragma unroll
            for (int mt = 0; mt < 2; mt++) {
                mma_bf16(acc[mt][nt], ah[mt], bh);   // hi*hi
                mma_bf16(acc[mt][nt], ah[mt], bl);   // hi*lo
                mma_bf16(acc[mt][nt], al[mt], bh);   // lo*hi
            }
        }
    }

    // ---- Epilogue: stage C to smem (reuse operand space), coalesced STG ----
    __syncthreads();   // all warps done reading xh/xl/wh/wl

    {
        float* ys = reinterpret_cast<float*>(smem + SM_YS);
        int r0 = wrow + (lane >> 2);
        int c0 = (lane & 3) * 2;
        #pragma unroll
        for (int mt = 0; mt < 2; mt++) {
            #pragma unroll
            for (int nt = 0; nt < 8; nt++) {
                float* p0 = ys + (r0 + mt * 16) * YS_STRIDE + nt * 8 + c0;
                float* p1 = ys + (r0 + mt * 16 + 8) * YS_STRIDE + nt * 8 + c0;
                *reinterpret_cast<float2*>(p0) =
                    make_float2(acc[mt][nt][0], acc[mt][nt][1]);
                *reinterpret_cast<float2*>(p1) =
                    make_float2(acc[mt][nt][2], acc[mt][nt][3]);
            }
        }
    }
    __syncthreads();

    // Coalesced store: 16 lanes cover one row's 64 floats
    {
        const float* ys = reinterpret_cast<const float*>(smem + SM_YS);
        #pragma unroll
        for (int r = 0; r < 16; r++) {
            int idx = tid + r * THREADS;            // 0..2047
            int row = idx >> 4;
            int c4  = idx & 15;
            float4 v = *reinterpret_cast<const float4*>(
                ys + row * YS_STRIDE + c4 * 4);
            *reinterpret_cast<float4*>(
                y + (size_t)(tok0 + row) * IN_CH + g * GS + c4 * 4) = v;
        }
    }
}

extern "C" void kernel_launch(void* const* d_in, const int* in_sizes, int n_in,
                              void* d_out, int out_size) {
    const float* x = (const float*)d_in[0];   // [8192, 4096] fp32
    const float* w = (const float*)d_in[1];   // [4096, 4096] fp32
    float* y = (float*)d_out;                 // [8192, 4096] fp32

    cudaFuncSetAttribute(group_linear_mma,
                         cudaFuncAttributeMaxDynamicSharedMemorySize, SM_TOTAL);
    dim3 grid(N_TOKENS / BLK_TOK, GROUPS);    // (64, 64)
    group_linear_mma<<<grid, THREADS, SM_TOTAL>>>(x, w, y);
}

// round 8
// speedup vs baseline: 1.6897x; 1.1446x over previous
#include <cuda_runtime.h>
#include <cuda_bf16.h>
#include <cstdint>

// GroupLinear: y[b, g*64+o] = sum_i x[b, g*64+i] * W[g*64+o, g*64+i]
// 64 independent [8192x64] x [64x64]^T GEMMs, fp32 in/out.
//
// mma.sync.m16n8k16 bf16 (compute_100-safe) with 2-term bf16 split:
//   x = xh+xl, W = wh+wl;  y ~= xh*wh + xh*wl + xl*wh  (drop lo*lo ~2^-16)
// R8: small CTAs for occupancy (BLK_TOK=64, warp=16 rows, acc=32 regs,
// 4-5 CTAs/SM) + ldmatrix.x4 fragment loads (4x fewer LDS issue slots).

#define GROUPS     64
#define GS         64
#define BLK_TOK    64
#define THREADS    128
#define IN_CH      4096
#define N_TOKENS   8192

// SMEM (bytes): bf16 tiles, row stride 72 halves (144 B) -> ldmatrix phases
// hit banks 4r..4r+3 for r=0..7: conflict-free.
#define XSTRIDE_H  72
#define ROWB       (XSTRIDE_H * 2)                       // 144 B per row
#define SM_XH      0
#define SM_XL      (SM_XH + BLK_TOK * ROWB)              // 9216
#define SM_WH      (SM_XL + BLK_TOK * ROWB)              // 18432
#define SM_WL      (SM_WH + GS * ROWB)                   // 27648
#define SM_TOTAL   (SM_WL + GS * ROWB)                   // 36864
// Epilogue staging reuses tile space (after syncthreads):
#define YS_STRIDE  68                                    // floats
#define SM_YS      0                                     // 64*68*4 = 17408 B

__device__ __forceinline__ uint32_t smem_u32(const void* p) {
    uint32_t a;
    asm("{ .reg .u64 t; cvta.to.shared.u64 t, %1; cvt.u32.u64 %0, t; }"
        : "=r"(a) : "l"(p));
    return a;
}

__device__ __forceinline__ uint32_t pack_bf16(float a, float b) {
    __nv_bfloat162 t = __floats2bfloat162_rn(a, b);
    return *reinterpret_cast<uint32_t*>(&t);
}
__device__ __forceinline__ void split_bf16(float v, float& hi, float& lo) {
    hi = __bfloat162float(__float2bfloat16(v));
    lo = v - hi;                    // exact residual
}

__device__ __forceinline__ uint4 ldm_x4(uint32_t addr) {
    uint4 r;
    asm volatile("ldmatrix.sync.aligned.m8n8.x4.shared.b16 {%0,%1,%2,%3}, [%4];"
                 : "=r"(r.x), "=r"(r.y), "=r"(r.z), "=r"(r.w) : "r"(addr));
    return r;
}

__device__ __forceinline__ void mma_bf16(float* c, const uint4& a,
                                         uint32_t b0, uint32_t b1) {
    asm volatile(
        "mma.sync.aligned.m16n8k16.row.col.f32.bf16.bf16.f32 "
        "{%0,%1,%2,%3}, {%4,%5,%6,%7}, {%8,%9}, {%0,%1,%2,%3};"
        : "+f"(c[0]), "+f"(c[1]), "+f"(c[2]), "+f"(c[3])
        : "r"(a.x), "r"(a.y), "r"(a.z), "r"(a.w), "r"(b0), "r"(b1));
}

__global__ __launch_bounds__(THREADS, 4)
void group_linear_mma(const float* __restrict__ x,
                      const float* __restrict__ w,
                      float* __restrict__ y) {
    extern __shared__ char smem[];
    const uint32_t sb = smem_u32(smem);
    const int tid  = threadIdx.x;
    const int wid  = tid >> 5;
    const int lane = tid & 31;
    const int g    = blockIdx.y;
    const int tok0 = blockIdx.x * BLK_TOK;

    // ---- Load W diagonal block g -> bf16 hi/lo smem (coalesced) ----
    // 64x64 f32 = 1024 float4; 8 per thread.
    {
        #pragma unroll
        for (int r = 0; r < 8; r++) {
            int idx = tid + r * THREADS;            // 0..1023
            int row = idx >> 4;                     // 0..63 (output o)
            int k4  = idx & 15;
            float4 v = *reinterpret_cast<const float4*>(
                w + (size_t)(g * GS + row) * IN_CH + g * GS + k4 * 4);
            float hx, lx, hy, ly, hz, lz, hw, lw;
            split_bf16(v.x, hx, lx); split_bf16(v.y, hy, ly);
            split_bf16(v.z, hz, lz); split_bf16(v.w, hw, lw);
            uint2 hp = make_uint2(pack_bf16(hx, hy), pack_bf16(hz, hw));
            uint2 lp = make_uint2(pack_bf16(lx, ly), pack_bf16(lz, lw));
            int off = row * ROWB + k4 * 8;
            *reinterpret_cast<uint2*>(smem + SM_WH + off) = hp;
            *reinterpret_cast<uint2*>(smem + SM_WL + off) = lp;
        }
    }

    // ---- Load x tile [64 x 64] -> bf16 hi/lo smem ----
    // 1024 float4; 8 per thread.
    {
        #pragma unroll
        for (int r = 0; r < 8; r++) {
            int idx = tid + r * THREADS;            // 0..1023
            int row = idx >> 4;                     // 0..63 (token)
            int k4  = idx & 15;
            float4 v = *reinterpret_cast<const float4*>(
                x + (size_t)(tok0 + row) * IN_CH + g * GS + k4 * 4);
            float hx, lx, hy, ly, hz, lz, hw, lw;
            split_bf16(v.x, hx, lx); split_bf16(v.y, hy, ly);
            split_bf16(v.z, hz, lz); split_bf16(v.w, hw, lw);
            uint2 hp = make_uint2(pack_bf16(hx, hy), pack_bf16(hz, hw));
            uint2 lp = make_uint2(pack_bf16(lx, ly), pack_bf16(lz, lw));
            int off = row * ROWB + k4 * 8;
            *reinterpret_cast<uint2*>(smem + SM_XH + off) = hp;
            *reinterpret_cast<uint2*>(smem + SM_XL + off) = lp;
        }
    }
    __syncthreads();

    // ---- Mainloop: warp owns M-rows [wid*16, wid*16+16), all N=64 ----
    const int wrow = wid * 16;

    // ldmatrix lane->address maps (canonical m16n8k16 fragment order):
    // A x4: mats {r0-7/k0-7, r8-15/k0-7, r0-7/k8-15, r8-15/k8-15}
    //   row = wrow + (lane&15), byte = kk*32 + (lane>>4)*16
    const uint32_t a_addr =
        sb + (uint32_t)((wrow + (lane & 15)) * ROWB + (lane >> 4) * 16);
    // B x4 per nt-pair: mats {n0-7/k0-7, n0-7/k8-15, n8-15/k0-7, n8-15/k8-15}
    //   regs -> {b0(nt0), b1(nt0), b0(nt1), b1(nt1)}
    const int n_local = (lane >> 4) * 8 + (lane & 7);
    const uint32_t b_addr =
        sb + (uint32_t)(n_local * ROWB + ((lane >> 3) & 1) * 16);

    float acc[8][4];
    #pragma unroll
    for (int nt = 0; nt < 8; nt++)
        #pragma unroll
        for (int i = 0; i < 4; i++)
            acc[nt][i] = 0.0f;

    #pragma unroll
    for (int kk = 0; kk < 4; kk++) {
        const uint32_t kb = kk * 32;               // 16 bf16 = 32 B
        uint4 ah = ldm_x4(a_addr + SM_XH + kb);
        uint4 al = ldm_x4(a_addr + SM_XL + kb);

        #pragma unroll
        for (int np = 0; np < 4; np++) {
            uint4 bh = ldm_x4(b_addr + SM_WH + np * 16 * ROWB + kb);
            uint4 bl = ldm_x4(b_addr + SM_WL + np * 16 * ROWB + kb);
            float* c0 = acc[np * 2];
            float* c1 = acc[np * 2 + 1];
            mma_bf16(c0, ah, bh.x, bh.y);    // hi*hi
            mma_bf16(c1, ah, bh.z, bh.w);
            mma_bf16(c0, ah, bl.x, bl.y);    // hi*lo
            mma_bf16(c1, ah, bl.z, bl.w);
            mma_bf16(c0, al, bh.x, bh.y);    // lo*hi
            mma_bf16(c1, al, bh.z, bh.w);
        }
    }

    // ---- Epilogue: stage C to smem (reuse tiles), coalesced STG ----
    __syncthreads();   // all warps done reading tiles

    {
        float* ys = reinterpret_cast<float*>(smem + SM_YS);
        int r0 = wrow + (lane >> 2);
        int c0 = (lane & 3) * 2;
        #pragma unroll
        for (int nt = 0; nt < 8; nt++) {
            *reinterpret_cast<float2*>(ys + r0 * YS_STRIDE + nt * 8 + c0) =
                make_float2(acc[nt][0], acc[nt][1]);
            *reinterpret_cast<float2*>(ys + (r0 + 8) * YS_STRIDE + nt * 8 + c0) =
                make_float2(acc[nt][2], acc[nt][3]);
        }
    }
    __syncthreads();

    // Coalesced store: 16 lanes cover one row's 64 floats
    {
        const float* ys = reinterpret_cast<const float*>(smem + SM_YS);
        #pragma unroll
        for (int r = 0; r < 8; r++) {
            int idx = tid + r * THREADS;            // 0..1023
            int row = idx >> 4;
            int c4  = idx & 15;
            float4 v = *reinterpret_cast<const float4*>(
                ys + row * YS_STRIDE + c4 * 4);
            *reinterpret_cast<float4*>(
                y + (size_t)(tok0 + row) * IN_CH + g * GS + c4 * 4) = v;
        }
    }
}

extern "C" void kernel_launch(void* const* d_in, const int* in_sizes, int n_in,
                              void* d_out, int out_size) {
    const float* x = (const float*)d_in[0];   // [8192, 4096] fp32
    const float* w = (const float*)d_in[1];   // [4096, 4096] fp32
    float* y = (float*)d_out;                 // [8192, 4096] fp32

    cudaFuncSetAttribute(group_linear_mma,
                         cudaFuncAttributeMaxDynamicSharedMemorySize, SM_TOTAL);
    dim3 grid(N_TOKENS / BLK_TOK, GROUPS);    // (128, 64)
    group_linear_mma<<<grid, THREADS, SM_TOTAL>>>(x, w, y);
}